// round 2
// baseline (speedup 1.0000x reference)
#include <cuda_runtime.h>
#include <cuda_bf16.h>
#include <math.h>

// Problem constants (fixed by the reference: B=4, T=2048, H=2048)
#define BB 4
#define TT 2048
#define HH 2048
#define MM (BB*TT)              // 8192 rows
#define CHUNK 128
#define NCHUNK (TT/CHUNK)       // 16 chunks

typedef unsigned long long u64;

// ---------------------------------------------------------------------------
// Scratch (device globals — no runtime allocation allowed)
// ---------------------------------------------------------------------------
__device__ float g_gate[(size_t)MM*HH];   // sigmoid(f)
__device__ float g_v[(size_t)MM*HH];      // silu(i)*(1-gate)
__device__ float g_gp[(size_t)MM*HH];     // g projection (needed at norm stage)
__device__ float g_o[(size_t)MM*HH];      // scan output, then normed output (in place)
__device__ float g_Ac[BB*NCHUNK*HH];      // per-chunk gate product
__device__ float g_Bc[BB*NCHUNK*HH];      // per-chunk local scan tail
__device__ float g_cr[BB*NCHUNK*HH];      // carry-in per chunk

__device__ __forceinline__ float sigf(float x) { return 1.0f/(1.0f+__expf(-x)); }

// Packed f32x2 helpers (sm_100+): one issue slot = 2 lane-FMAs
__device__ __forceinline__ void ffma2(u64 &acc, u64 a, u64 b) {
    asm("fma.rn.f32x2 %0, %1, %2, %0;" : "+l"(acc) : "l"(a), "l"(b));
}
__device__ __forceinline__ u64 pack2(float lo, float hi) {
    u64 r; asm("mov.b64 %0, {%1, %2};" : "=l"(r) : "f"(lo), "f"(hi)); return r;
}
__device__ __forceinline__ float2 unpack2(u64 v) {
    float2 f; asm("mov.b64 {%0, %1}, %2;" : "=f"(f.x), "=f"(f.y) : "l"(v)); return f;
}

// ---------------------------------------------------------------------------
// GEMM tiling: C[m,n] = sum_k A[m,k]*W[n,k]   (both row-major, k contiguous)
// 64x64 block tile, 16 k-slice, 4x4 microtile, 256 threads, double-buffered
// ---------------------------------------------------------------------------
#define BM 64
#define BN 64
#define BKK 16
#define NT (HH/BKK)   // 128 k-tiles

// Fused projection GEMM: computes i,f,g tiles together (shared A tile),
// applies gating nonlinearity in the epilogue.
__global__ __launch_bounds__(256, 2) void proj3_kernel(
    const float* __restrict__ X, const float* __restrict__ Wi,
    const float* __restrict__ Wf, const float* __restrict__ Wg)
{
    __shared__ __align__(16) float As[2][BKK][BM];
    __shared__ __align__(16) float Bs[3][2][BKK][BN];
    const int tid  = threadIdx.x;
    const int bm   = blockIdx.y * BM;
    const int bn   = blockIdx.x * BN;
    const int lrow = tid >> 2;            // 0..63
    const int lcol = (tid & 3) << 2;      // 0,4,8,12
    const int tx   = tid & 15;            // n-dir microtile
    const int ty   = tid >> 4;            // m-dir microtile

    u64 acc0[4][2] = {}, acc1[4][2] = {}, acc2[4][2] = {};

    const float* Ag  = X  + (size_t)(bm + lrow)*HH + lcol;
    const float* Wig = Wi + (size_t)(bn + lrow)*HH + lcol;
    const float* Wfg = Wf + (size_t)(bn + lrow)*HH + lcol;
    const float* Wgg = Wg + (size_t)(bn + lrow)*HH + lcol;

    // prime buffer 0
    {
        float4 a4 = *(const float4*)(Ag);
        float4 b0 = *(const float4*)(Wig);
        float4 b1 = *(const float4*)(Wfg);
        float4 b2 = *(const float4*)(Wgg);
        As[0][lcol+0][lrow]=a4.x; As[0][lcol+1][lrow]=a4.y; As[0][lcol+2][lrow]=a4.z; As[0][lcol+3][lrow]=a4.w;
        Bs[0][0][lcol+0][lrow]=b0.x; Bs[0][0][lcol+1][lrow]=b0.y; Bs[0][0][lcol+2][lrow]=b0.z; Bs[0][0][lcol+3][lrow]=b0.w;
        Bs[1][0][lcol+0][lrow]=b1.x; Bs[1][0][lcol+1][lrow]=b1.y; Bs[1][0][lcol+2][lrow]=b1.z; Bs[1][0][lcol+3][lrow]=b1.w;
        Bs[2][0][lcol+0][lrow]=b2.x; Bs[2][0][lcol+1][lrow]=b2.y; Bs[2][0][lcol+2][lrow]=b2.z; Bs[2][0][lcol+3][lrow]=b2.w;
    }
    __syncthreads();

    for (int kt = 0; kt < NT; kt++) {
        const int buf = kt & 1;
        float4 na, nb0, nb1, nb2;
        const bool more = (kt + 1 < NT);
        if (more) {
            const int k0 = (kt + 1) * BKK;
            na  = *(const float4*)(Ag  + k0);
            nb0 = *(const float4*)(Wig + k0);
            nb1 = *(const float4*)(Wfg + k0);
            nb2 = *(const float4*)(Wgg + k0);
        }
#pragma unroll
        for (int k = 0; k < BKK; k++) {
            float4 af = *(const float4*)&As[buf][k][ty*4];
            float4 p  = *(const float4*)&Bs[0][buf][k][tx*4];
            float4 q  = *(const float4*)&Bs[1][buf][k][tx*4];
            float4 r  = *(const float4*)&Bs[2][buf][k][tx*4];
            u64 p01 = pack2(p.x, p.y), p23 = pack2(p.z, p.w);
            u64 q01 = pack2(q.x, q.y), q23 = pack2(q.z, q.w);
            u64 r01 = pack2(r.x, r.y), r23 = pack2(r.z, r.w);
            float av[4] = {af.x, af.y, af.z, af.w};
#pragma unroll
            for (int i = 0; i < 4; i++) {
                u64 aa = pack2(av[i], av[i]);
                ffma2(acc0[i][0], aa, p01); ffma2(acc0[i][1], aa, p23);
                ffma2(acc1[i][0], aa, q01); ffma2(acc1[i][1], aa, q23);
                ffma2(acc2[i][0], aa, r01); ffma2(acc2[i][1], aa, r23);
            }
        }
        if (more) {
            const int nb = buf ^ 1;
            As[nb][lcol+0][lrow]=na.x; As[nb][lcol+1][lrow]=na.y; As[nb][lcol+2][lrow]=na.z; As[nb][lcol+3][lrow]=na.w;
            Bs[0][nb][lcol+0][lrow]=nb0.x; Bs[0][nb][lcol+1][lrow]=nb0.y; Bs[0][nb][lcol+2][lrow]=nb0.z; Bs[0][nb][lcol+3][lrow]=nb0.w;
            Bs[1][nb][lcol+0][lrow]=nb1.x; Bs[1][nb][lcol+1][lrow]=nb1.y; Bs[1][nb][lcol+2][lrow]=nb1.z; Bs[1][nb][lcol+3][lrow]=nb1.w;
            Bs[2][nb][lcol+0][lrow]=nb2.x; Bs[2][nb][lcol+1][lrow]=nb2.y; Bs[2][nb][lcol+2][lrow]=nb2.z; Bs[2][nb][lcol+3][lrow]=nb2.w;
            __syncthreads();
        }
    }

    // Epilogue: gate = sigmoid(f); v = silu(i)*(1-gate); keep raw g.
#pragma unroll
    for (int i = 0; i < 4; i++) {
        const int m = bm + ty*4 + i;
        const size_t off = (size_t)m*HH + bn + tx*4;
        float2 i01 = unpack2(acc0[i][0]), i23 = unpack2(acc0[i][1]);
        float2 f01 = unpack2(acc1[i][0]), f23 = unpack2(acc1[i][1]);
        float2 p01 = unpack2(acc2[i][0]), p23 = unpack2(acc2[i][1]);
        float iv[4] = {i01.x, i01.y, i23.x, i23.y};
        float fv[4] = {f01.x, f01.y, f23.x, f23.y};
        float pv[4] = {p01.x, p01.y, p23.x, p23.y};
        float g4[4], v4[4];
#pragma unroll
        for (int j = 0; j < 4; j++) {
            float gate = sigf(fv[j]);
            g4[j] = gate;
            v4[j] = iv[j] * sigf(iv[j]) * (1.0f - gate);
        }
        *(float4*)&g_gate[off] = make_float4(g4[0],g4[1],g4[2],g4[3]);
        *(float4*)&g_v[off]    = make_float4(v4[0],v4[1],v4[2],v4[3]);
        *(float4*)&g_gp[off]   = make_float4(pv[0],pv[1],pv[2],pv[3]);
    }
}

// Output GEMM: out[m,n] = sum_k g_o[m,k]*Wo[n,k]
__global__ __launch_bounds__(256, 2) void gemm_out_kernel(
    const float* __restrict__ Wo, float* __restrict__ C)
{
    __shared__ __align__(16) float As[2][BKK][BM];
    __shared__ __align__(16) float Bs[2][BKK][BN];
    const int tid  = threadIdx.x;
    const int bm   = blockIdx.y * BM;
    const int bn   = blockIdx.x * BN;
    const int lrow = tid >> 2;
    const int lcol = (tid & 3) << 2;
    const int tx   = tid & 15;
    const int ty   = tid >> 4;

    u64 acc[4][2] = {};

    const float* Ag = g_o + (size_t)(bm + lrow)*HH + lcol;
    const float* Bg = Wo  + (size_t)(bn + lrow)*HH + lcol;

    {
        float4 a4 = *(const float4*)(Ag);
        float4 b4 = *(const float4*)(Bg);
        As[0][lcol+0][lrow]=a4.x; As[0][lcol+1][lrow]=a4.y; As[0][lcol+2][lrow]=a4.z; As[0][lcol+3][lrow]=a4.w;
        Bs[0][lcol+0][lrow]=b4.x; Bs[0][lcol+1][lrow]=b4.y; Bs[0][lcol+2][lrow]=b4.z; Bs[0][lcol+3][lrow]=b4.w;
    }
    __syncthreads();

    for (int kt = 0; kt < NT; kt++) {
        const int buf = kt & 1;
        float4 na, nb;
        const bool more = (kt + 1 < NT);
        if (more) {
            const int k0 = (kt + 1) * BKK;
            na = *(const float4*)(Ag + k0);
            nb = *(const float4*)(Bg + k0);
        }
#pragma unroll
        for (int k = 0; k < BKK; k++) {
            float4 af = *(const float4*)&As[buf][k][ty*4];
            float4 bf = *(const float4*)&Bs[buf][k][tx*4];
            u64 b01 = pack2(bf.x, bf.y), b23 = pack2(bf.z, bf.w);
            float av[4] = {af.x, af.y, af.z, af.w};
#pragma unroll
            for (int i = 0; i < 4; i++) {
                u64 aa = pack2(av[i], av[i]);
                ffma2(acc[i][0], aa, b01);
                ffma2(acc[i][1], aa, b23);
            }
        }
        if (more) {
            const int nb2 = buf ^ 1;
            As[nb2][lcol+0][lrow]=na.x; As[nb2][lcol+1][lrow]=na.y; As[nb2][lcol+2][lrow]=na.z; As[nb2][lcol+3][lrow]=na.w;
            Bs[nb2][lcol+0][lrow]=nb.x; Bs[nb2][lcol+1][lrow]=nb.y; Bs[nb2][lcol+2][lrow]=nb.z; Bs[nb2][lcol+3][lrow]=nb.w;
            __syncthreads();
        }
    }
#pragma unroll
    for (int i = 0; i < 4; i++) {
        const int m = bm + ty*4 + i;
        const size_t off = (size_t)m*HH + bn + tx*4;
        float2 c01 = unpack2(acc[i][0]);
        float2 c23 = unpack2(acc[i][1]);
        *(float4*)&C[off] = make_float4(c01.x, c01.y, c23.x, c23.y);
    }
}

// ---------------------------------------------------------------------------
// Chunked exact linear scan: h_t = gate_t*h_{t-1} + v_t  along T per (b,d)
// ---------------------------------------------------------------------------
// Pass 1: per chunk, compute A = prod(gate), B = scan-from-zero tail.
__global__ void scan_part1()
{
    const int d = blockIdx.x * blockDim.x + threadIdx.x;   // 0..H-1
    const int c = blockIdx.y;                              // chunk
    const int b = blockIdx.z;                              // batch
    size_t base = ((size_t)(b*TT + c*CHUNK))*HH + d;
    float A = 1.0f, Bv = 0.0f;
#pragma unroll 4
    for (int t = 0; t < CHUNK; t++) {
        float g  = g_gate[base + (size_t)t*HH];
        float vv = g_v   [base + (size_t)t*HH];
        Bv = fmaf(g, Bv, vv);
        A *= g;
    }
    const size_t co = ((size_t)(b*NCHUNK + c))*HH + d;
    g_Ac[co] = A;
    g_Bc[co] = Bv;
}

// Pass 2: sequential carry combine across the 16 chunks (tiny).
__global__ void scan_part2()
{
    const int idx = blockIdx.x * blockDim.x + threadIdx.x; // 0..B*H-1
    const int b = idx / HH, d = idx % HH;
    float h = 0.0f;
    for (int c = 0; c < NCHUNK; c++) {
        const size_t co = ((size_t)(b*NCHUNK + c))*HH + d;
        g_cr[co] = h;                       // carry INTO chunk c
        h = fmaf(g_Ac[co], h, g_Bc[co]);
    }
}

// Pass 3: re-scan each chunk with its carry, writing o.
__global__ void scan_part3()
{
    const int d = blockIdx.x * blockDim.x + threadIdx.x;
    const int c = blockIdx.y;
    const int b = blockIdx.z;
    size_t base = ((size_t)(b*TT + c*CHUNK))*HH + d;
    float h = g_cr[((size_t)(b*NCHUNK + c))*HH + d];
#pragma unroll 4
    for (int t = 0; t < CHUNK; t++) {
        float g  = g_gate[base + (size_t)t*HH];
        float vv = g_v   [base + (size_t)t*HH];
        h = fmaf(g, h, vv);
        g_o[base + (size_t)t*HH] = h;
    }
}

// ---------------------------------------------------------------------------
// Gated RMSNorm: o = rmsnorm(o)*w * g*sigmoid(g), in place. One block per row.
// ---------------------------------------------------------------------------
__global__ __launch_bounds__(256) void norm_kernel(const float* __restrict__ w)
{
    const int m = blockIdx.x;
    const size_t row = (size_t)m * HH;
    float s = 0.0f;
    for (int d = threadIdx.x; d < HH; d += 256) {
        float x = g_o[row + d];
        s = fmaf(x, x, s);
    }
    __shared__ float red[8];
#pragma unroll
    for (int o = 16; o; o >>= 1) s += __shfl_xor_sync(0xffffffffu, s, o);
    if ((threadIdx.x & 31) == 0) red[threadIdx.x >> 5] = s;
    __syncthreads();
    if (threadIdx.x < 8) {
        float t = red[threadIdx.x];
#pragma unroll
        for (int o = 4; o; o >>= 1) t += __shfl_xor_sync(0xffu, t, o);
        if (threadIdx.x == 0) red[0] = t;
    }
    __syncthreads();
    const float rms = rsqrtf(red[0] / (float)HH + 1e-5f);
    for (int d = threadIdx.x; d < HH; d += 256) {
        float gp = g_gp[row + d];
        g_o[row + d] = g_o[row + d] * rms * w[d] * gp * sigf(gp);
    }
}

// ---------------------------------------------------------------------------
// Launch: metadata order = hidden_states, Wi, Wf, Wg, Wo, gnorm_w; output fp32
// ---------------------------------------------------------------------------
extern "C" void kernel_launch(void* const* d_in, const int* in_sizes, int n_in,
                              void* d_out, int out_size)
{
    const float* X  = (const float*)d_in[0];
    const float* Wi = (const float*)d_in[1];
    const float* Wf = (const float*)d_in[2];
    const float* Wg = (const float*)d_in[3];
    const float* Wo = (const float*)d_in[4];
    const float* gw = (const float*)d_in[5];
    float* out = (float*)d_out;

    dim3 gemm_grid(HH/BN, MM/BM);   // (32, 128)
    proj3_kernel<<<gemm_grid, 256>>>(X, Wi, Wf, Wg);

    dim3 scan_grid(HH/256, NCHUNK, BB);  // (8, 16, 4)
    scan_part1<<<scan_grid, 256>>>();
    scan_part2<<<(BB*HH)/256, 256>>>();
    scan_part3<<<scan_grid, 256>>>();

    norm_kernel<<<MM, 256>>>(gw);

    gemm_out_kernel<<<gemm_grid, 256>>>(Wo, out);
}

// round 4
// speedup vs baseline: 2.7604x; 2.7604x over previous
#include <cuda_runtime.h>
#include <cuda_bf16.h>
#include <cstdint>
#include <math.h>

// Problem constants (fixed: B=4, T=2048, H=2048)
#define BB 4
#define TT 2048
#define HH 2048
#define MM (BB*TT)              // 8192 rows
#define CHUNK 128
#define NCHUNK (TT/CHUNK)       // 16 chunks

// ---------------------------------------------------------------------------
// Scratch (device globals — no runtime allocation allowed)
// ---------------------------------------------------------------------------
__device__ float g_gate[(size_t)MM*HH];   // raw i, then sigmoid(f)
__device__ float g_v[(size_t)MM*HH];      // raw f, then swiglu value
__device__ float g_gp[(size_t)MM*HH];     // raw g projection
__device__ float g_o[(size_t)MM*HH];      // scan output / normed output
__device__ float g_Ac[BB*NCHUNK*HH];
__device__ float g_Bc[BB*NCHUNK*HH];
__device__ float g_cr[BB*NCHUNK*HH];
// bf16 split operands: X (reused for normed o), 4 weights
__device__ __nv_bfloat16 g_Xh[(size_t)MM*HH];
__device__ __nv_bfloat16 g_Xl[(size_t)MM*HH];
__device__ __nv_bfloat16 g_Wh[4][(size_t)HH*HH];
__device__ __nv_bfloat16 g_Wl[4][(size_t)HH*HH];

__device__ __forceinline__ float sigf(float x) { return 1.0f/(1.0f+__expf(-x)); }

// ---------------------------------------------------------------------------
// PTX helpers (all sm_80-era -> valid on compute_100)
// ---------------------------------------------------------------------------
__device__ __forceinline__ uint32_t smem_u32(const void* p) {
    uint32_t a; asm("{ .reg .u64 t; cvta.to.shared.u64 t, %1; cvt.u32.u64 %0, t; }" : "=r"(a) : "l"(p));
    return a;
}
__device__ __forceinline__ void cp16(uint32_t saddr, const void* g) {
    asm volatile("cp.async.cg.shared.global [%0], [%1], 16;" :: "r"(saddr), "l"(g));
}
#define CP_COMMIT() asm volatile("cp.async.commit_group;" ::: "memory")
#define CP_WAIT1()  asm volatile("cp.async.wait_group 1;" ::: "memory")
#define CP_WAIT0()  asm volatile("cp.async.wait_group 0;" ::: "memory")

__device__ __forceinline__ void ldm_x4(uint32_t a, uint32_t* r) {
    asm volatile("ldmatrix.sync.aligned.m8n8.x4.shared.b16 {%0,%1,%2,%3}, [%4];"
        : "=r"(r[0]), "=r"(r[1]), "=r"(r[2]), "=r"(r[3]) : "r"(a));
}
__device__ __forceinline__ void mma16816(float* c, const uint32_t* a, const uint32_t* b) {
    asm volatile("mma.sync.aligned.m16n8k16.row.col.f32.bf16.bf16.f32 "
        "{%0,%1,%2,%3}, {%4,%5,%6,%7}, {%8,%9}, {%0,%1,%2,%3};"
        : "+f"(c[0]), "+f"(c[1]), "+f"(c[2]), "+f"(c[3])
        : "r"(a[0]), "r"(a[1]), "r"(a[2]), "r"(a[3]), "r"(b[0]), "r"(b[1]));
}

// ---------------------------------------------------------------------------
// bf16 hi/lo split converters
// ---------------------------------------------------------------------------
__device__ __forceinline__ void split4(float4 x, __nv_bfloat16* h, __nv_bfloat16* l) {
    float xs[4] = {x.x, x.y, x.z, x.w};
#pragma unroll
    for (int j = 0; j < 4; j++) {
        __nv_bfloat16 hv = __float2bfloat16(xs[j]);
        h[j] = hv;
        l[j] = __float2bfloat16(xs[j] - __bfloat162float(hv));
    }
}
__global__ __launch_bounds__(256) void cvt_x_kernel(const float* __restrict__ src) {
    size_t i = ((size_t)blockIdx.x * 256 + threadIdx.x) * 4;
    __nv_bfloat16 h[4], l[4];
    split4(*(const float4*)(src + i), h, l);
    *(uint2*)&g_Xh[i] = *(uint2*)h;
    *(uint2*)&g_Xl[i] = *(uint2*)l;
}
__global__ __launch_bounds__(256) void cvt_w_kernel(const float* __restrict__ src, int w) {
    size_t i = ((size_t)blockIdx.x * 256 + threadIdx.x) * 4;
    __nv_bfloat16 h[4], l[4];
    split4(*(const float4*)(src + i), h, l);
    *(uint2*)&g_Wh[w][i] = *(uint2*)h;
    *(uint2*)&g_Wl[w][i] = *(uint2*)l;
}
__global__ __launch_bounds__(256) void cvt_o_kernel() {
    size_t i = ((size_t)blockIdx.x * 256 + threadIdx.x) * 4;
    __nv_bfloat16 h[4], l[4];
    split4(*(const float4*)(g_o + i), h, l);
    *(uint2*)&g_Xh[i] = *(uint2*)h;
    *(uint2*)&g_Xl[i] = *(uint2*)l;
}

// ===========================================================================
// Generic split-bf16 GEMM on mma.sync: C[m,n] = sum_k A[m,k] * W[n,k]
// CTA 128x128, K-chunk 32, 8 warps (warp tile 32x64), cp.async double buffer.
// Smem per stage: Ah | Al | Bh | Bl, each 128 rows x 32 bf16 padded to 80B/row.
// ===========================================================================
#define KC 32
#define ROWB 80                // padded row stride (bytes): 20 banks, conflict-free
#define MATB (128*ROWB)        // 10240 B per matrix
#define STGB (4*MATB)          // 40960 B per stage
#define NKC (HH/KC)            // 64 k-iterations

__global__ __launch_bounds__(256, 2) void gemm_mma(
    const __nv_bfloat16* __restrict__ xh, const __nv_bfloat16* __restrict__ xl,
    int wbase,
    float* __restrict__ C0, float* __restrict__ C1, float* __restrict__ C2)
{
    extern __shared__ __align__(16) char smem[];
    const uint32_t sb = smem_u32(smem);
    const int tid = threadIdx.x, lane = tid & 31, wid = tid >> 5;
    const int wm = wid >> 1, wn = wid & 1;           // 4x2 warp grid
    const int bm = blockIdx.y * 128, bn = blockIdx.x * 128;
    const int w = wbase + blockIdx.z;
    const __nv_bfloat16* wh = g_Wh[w];
    const __nv_bfloat16* wl = g_Wl[w];
    float* C = (blockIdx.z == 0) ? C0 : (blockIdx.z == 1) ? C1 : C2;

    float acc[2][8][4] = {};

    // cp.async stage loader: 2048 16B vectors, 8 per thread
    auto load_stage = [&](int buf, int k0) {
        const uint32_t sbase = sb + buf * STGB;
#pragma unroll
        for (int i = 0; i < 8; i++) {
            int idx = i * 256 + tid;
            int mat = idx >> 9;          // 0:Ah 1:Al 2:Bh 3:Bl (const after unroll)
            int rem = idx & 511;
            int r = rem >> 2, vv = rem & 3;
            const __nv_bfloat16* base = (mat == 0) ? xh : (mat == 1) ? xl
                                      : (mat == 2) ? wh : wl;
            int row0 = (mat < 2) ? bm : bn;
            cp16(sbase + mat * MATB + r * ROWB + vv * 16,
                 base + (size_t)(row0 + r) * HH + k0 + vv * 8);
        }
    };

    // ldmatrix per-lane address components
    const uint32_t aRowOff = (uint32_t)((wm * 32 + (lane & 15)) * ROWB + (lane >> 4) * 16);
    const uint32_t bRowOff = (uint32_t)((wn * 64 + ((lane >> 4) << 3) + (lane & 7)) * ROWB
                                        + ((lane >> 3) & 1) * 16);

    load_stage(0, 0);
    CP_COMMIT();

    for (int c = 0; c < NKC; c++) {
        const int buf = c & 1;
        if (c + 1 < NKC) {
            load_stage(buf ^ 1, (c + 1) * KC);
            CP_COMMIT();
            CP_WAIT1();
        } else {
            CP_WAIT0();
        }
        __syncthreads();

        const uint32_t s0 = sb + buf * STGB;
#pragma unroll
        for (int kg = 0; kg < 2; kg++) {
            const uint32_t kOff = kg * 32;     // 16 bf16 = 32B
            uint32_t ah[2][4], al[2][4];
#pragma unroll
            for (int mt = 0; mt < 2; mt++) {
                ldm_x4(s0 + 0    + mt * 16 * ROWB + kOff + aRowOff, ah[mt]);
                ldm_x4(s0 + MATB + mt * 16 * ROWB + kOff + aRowOff, al[mt]);
            }
#pragma unroll
            for (int p = 0; p < 4; p++) {      // n-tile pairs
                uint32_t bh4[4], bl4[4];
                ldm_x4(s0 + 2*MATB + p * 16 * ROWB + kOff + bRowOff, bh4);
                ldm_x4(s0 + 3*MATB + p * 16 * ROWB + kOff + bRowOff, bl4);
#pragma unroll
                for (int mt = 0; mt < 2; mt++) {
                    mma16816(acc[mt][2*p],   ah[mt], &bh4[0]);
                    mma16816(acc[mt][2*p],   ah[mt], &bl4[0]);
                    mma16816(acc[mt][2*p],   al[mt], &bh4[0]);
                    mma16816(acc[mt][2*p+1], ah[mt], &bh4[2]);
                    mma16816(acc[mt][2*p+1], ah[mt], &bl4[2]);
                    mma16816(acc[mt][2*p+1], al[mt], &bh4[2]);
                }
            }
        }
        __syncthreads();
    }

    // Epilogue: fragment (c0,c1)@row gid, (c2,c3)@row gid+8; cols 2*tig..+1
#pragma unroll
    for (int mt = 0; mt < 2; mt++) {
        const int r0 = bm + wm * 32 + mt * 16 + (lane >> 2);
#pragma unroll
        for (int nt = 0; nt < 8; nt++) {
            const int col = bn + wn * 64 + nt * 8 + (lane & 3) * 2;
            *(float2*)&C[(size_t)r0 * HH + col]       = make_float2(acc[mt][nt][0], acc[mt][nt][1]);
            *(float2*)&C[(size_t)(r0 + 8) * HH + col] = make_float2(acc[mt][nt][2], acc[mt][nt][3]);
        }
    }
}

// ---------------------------------------------------------------------------
// Elementwise gating: gate=sigmoid(f), v=silu(i)*(1-gate); g stays raw in g_gp
// ---------------------------------------------------------------------------
__global__ __launch_bounds__(256) void gating_kernel()
{
    size_t i4 = ((size_t)blockIdx.x * 256 + threadIdx.x) * 4;
    float4 iv = *(float4*)&g_gate[i4];
    float4 fv = *(float4*)&g_v[i4];
    float ivs[4] = {iv.x, iv.y, iv.z, iv.w};
    float fvs[4] = {fv.x, fv.y, fv.z, fv.w};
    float g4[4], v4[4];
#pragma unroll
    for (int j = 0; j < 4; j++) {
        float gate = sigf(fvs[j]);
        g4[j] = gate;
        v4[j] = ivs[j] * sigf(ivs[j]) * (1.0f - gate);
    }
    *(float4*)&g_gate[i4] = make_float4(g4[0], g4[1], g4[2], g4[3]);
    *(float4*)&g_v[i4]    = make_float4(v4[0], v4[1], v4[2], v4[3]);
}

// ---------------------------------------------------------------------------
// Chunked exact linear scan (unchanged, passing)
// ---------------------------------------------------------------------------
__global__ void scan_part1()
{
    const int d = blockIdx.x * blockDim.x + threadIdx.x;
    const int c = blockIdx.y, b = blockIdx.z;
    size_t base = ((size_t)(b*TT + c*CHUNK))*HH + d;
    float A = 1.0f, Bv = 0.0f;
#pragma unroll 4
    for (int t = 0; t < CHUNK; t++) {
        float g  = g_gate[base + (size_t)t*HH];
        float vv = g_v   [base + (size_t)t*HH];
        Bv = fmaf(g, Bv, vv);
        A *= g;
    }
    const size_t co = ((size_t)(b*NCHUNK + c))*HH + d;
    g_Ac[co] = A; g_Bc[co] = Bv;
}
__global__ void scan_part2()
{
    const int idx = blockIdx.x * blockDim.x + threadIdx.x;
    const int b = idx / HH, d = idx % HH;
    float h = 0.0f;
    for (int c = 0; c < NCHUNK; c++) {
        const size_t co = ((size_t)(b*NCHUNK + c))*HH + d;
        g_cr[co] = h;
        h = fmaf(g_Ac[co], h, g_Bc[co]);
    }
}
__global__ void scan_part3()
{
    const int d = blockIdx.x * blockDim.x + threadIdx.x;
    const int c = blockIdx.y, b = blockIdx.z;
    size_t base = ((size_t)(b*TT + c*CHUNK))*HH + d;
    float h = g_cr[((size_t)(b*NCHUNK + c))*HH + d];
#pragma unroll 4
    for (int t = 0; t < CHUNK; t++) {
        float g  = g_gate[base + (size_t)t*HH];
        float vv = g_v   [base + (size_t)t*HH];
        h = fmaf(g, h, vv);
        g_o[base + (size_t)t*HH] = h;
    }
}

// ---------------------------------------------------------------------------
// Gated RMSNorm (unchanged, passing)
// ---------------------------------------------------------------------------
__global__ __launch_bounds__(256) void norm_kernel(const float* __restrict__ w)
{
    const int m = blockIdx.x;
    const size_t row = (size_t)m * HH;
    float s = 0.0f;
    for (int d = threadIdx.x; d < HH; d += 256) {
        float x = g_o[row + d];
        s = fmaf(x, x, s);
    }
    __shared__ float red[8];
#pragma unroll
    for (int o = 16; o; o >>= 1) s += __shfl_xor_sync(0xffffffffu, s, o);
    if ((threadIdx.x & 31) == 0) red[threadIdx.x >> 5] = s;
    __syncthreads();
    if (threadIdx.x < 8) {
        float t = red[threadIdx.x];
#pragma unroll
        for (int o = 4; o; o >>= 1) t += __shfl_xor_sync(0xffu, t, o);
        if (threadIdx.x == 0) red[0] = t;
    }
    __syncthreads();
    const float rms = rsqrtf(red[0] / (float)HH + 1e-5f);
    for (int d = threadIdx.x; d < HH; d += 256) {
        float gp = g_gp[row + d];
        g_o[row + d] = g_o[row + d] * rms * w[d] * gp * sigf(gp);
    }
}

// ---------------------------------------------------------------------------
// Launch
// ---------------------------------------------------------------------------
extern "C" void kernel_launch(void* const* d_in, const int* in_sizes, int n_in,
                              void* d_out, int out_size)
{
    const float* X  = (const float*)d_in[0];
    const float* Wi = (const float*)d_in[1];
    const float* Wf = (const float*)d_in[2];
    const float* Wg = (const float*)d_in[3];
    const float* Wo = (const float*)d_in[4];
    const float* gw = (const float*)d_in[5];
    float* out = (float*)d_out;

    cudaFuncSetAttribute(gemm_mma, cudaFuncAttributeMaxDynamicSharedMemorySize, 2 * STGB);

    // bf16 hi/lo splits
    cvt_x_kernel<<<(size_t)MM*HH/1024, 256>>>(X);
    cvt_w_kernel<<<(size_t)HH*HH/1024, 256>>>(Wi, 0);
    cvt_w_kernel<<<(size_t)HH*HH/1024, 256>>>(Wf, 1);
    cvt_w_kernel<<<(size_t)HH*HH/1024, 256>>>(Wg, 2);
    cvt_w_kernel<<<(size_t)HH*HH/1024, 256>>>(Wo, 3);

    // i/f/g projections (raw) via tensor cores
    float *pi, *pf, *pg2;
    cudaGetSymbolAddress((void**)&pi,  g_gate);
    cudaGetSymbolAddress((void**)&pf,  g_v);
    cudaGetSymbolAddress((void**)&pg2, g_gp);
    const __nv_bfloat16 *xh, *xl;
    cudaGetSymbolAddress((void**)&xh, g_Xh);
    cudaGetSymbolAddress((void**)&xl, g_Xl);

    gemm_mma<<<dim3(HH/128, MM/128, 3), 256, 2*STGB>>>(xh, xl, 0, pi, pf, pg2);

    // gating + linear recurrence
    gating_kernel<<<(size_t)MM*HH/1024, 256>>>();
    dim3 scan_grid(HH/256, NCHUNK, BB);
    scan_part1<<<scan_grid, 256>>>();
    scan_part2<<<(BB*HH)/256, 256>>>();
    scan_part3<<<scan_grid, 256>>>();

    // gated RMSNorm, split o to bf16 pair
    norm_kernel<<<MM, 256>>>(gw);
    cvt_o_kernel<<<(size_t)MM*HH/1024, 256>>>();

    // output projection -> d_out
    gemm_mma<<<dim3(HH/128, MM/128, 1), 256, 2*STGB>>>(xh, xl, 3, out, out, out);
}

// round 5
// speedup vs baseline: 2.8871x; 1.0459x over previous
#include <cuda_runtime.h>
#include <cuda_bf16.h>
#include <cstdint>
#include <math.h>

// Problem constants (fixed: B=4, T=2048, H=2048)
#define BB 4
#define TT 2048
#define HH 2048
#define MM (BB*TT)              // 8192 rows
#define CHUNK 128
#define NCHUNK (TT/CHUNK)       // 16 chunks

// ---------------------------------------------------------------------------
// Scratch (device globals — no runtime allocation allowed)
// ---------------------------------------------------------------------------
__device__ float g_gate[(size_t)MM*HH];   // raw i -> sigmoid(f) after part1
__device__ float g_v[(size_t)MM*HH];      // raw f -> swiglu value after part1
__device__ float g_gp[(size_t)MM*HH];     // raw g projection
__device__ float g_o[(size_t)MM*HH];      // scan output
__device__ float g_Ac[BB*NCHUNK*HH];
__device__ float g_Bc[BB*NCHUNK*HH];
__device__ float g_cr[BB*NCHUNK*HH];
// bf16 split operands: X (reused for normed o), 4 weights
__device__ __nv_bfloat16 g_Xh[(size_t)MM*HH];
__device__ __nv_bfloat16 g_Xl[(size_t)MM*HH];
__device__ __nv_bfloat16 g_Wh[4][(size_t)HH*HH];
__device__ __nv_bfloat16 g_Wl[4][(size_t)HH*HH];

__device__ __forceinline__ float sigf(float x) { return 1.0f/(1.0f+__expf(-x)); }

// ---------------------------------------------------------------------------
// PTX helpers (sm_80-era -> valid on compute_100)
// ---------------------------------------------------------------------------
__device__ __forceinline__ uint32_t smem_u32(const void* p) {
    uint32_t a; asm("{ .reg .u64 t; cvta.to.shared.u64 t, %1; cvt.u32.u64 %0, t; }" : "=r"(a) : "l"(p));
    return a;
}
__device__ __forceinline__ void cp16(uint32_t saddr, const void* g) {
    asm volatile("cp.async.cg.shared.global [%0], [%1], 16;" :: "r"(saddr), "l"(g));
}
#define CP_COMMIT() asm volatile("cp.async.commit_group;" ::: "memory")
#define CP_WAIT0()  asm volatile("cp.async.wait_group 0;" ::: "memory")

__device__ __forceinline__ void ldm_x4(uint32_t a, uint32_t* r) {
    asm volatile("ldmatrix.sync.aligned.m8n8.x4.shared.b16 {%0,%1,%2,%3}, [%4];"
        : "=r"(r[0]), "=r"(r[1]), "=r"(r[2]), "=r"(r[3]) : "r"(a));
}
__device__ __forceinline__ void mma16816(float* c, const uint32_t* a, const uint32_t* b) {
    asm volatile("mma.sync.aligned.m16n8k16.row.col.f32.bf16.bf16.f32 "
        "{%0,%1,%2,%3}, {%4,%5,%6,%7}, {%8,%9}, {%0,%1,%2,%3};"
        : "+f"(c[0]), "+f"(c[1]), "+f"(c[2]), "+f"(c[3])
        : "r"(a[0]), "r"(a[1]), "r"(a[2]), "r"(a[3]), "r"(b[0]), "r"(b[1]));
}

// ---------------------------------------------------------------------------
// bf16 hi/lo split converters
// ---------------------------------------------------------------------------
__device__ __forceinline__ void split4(float4 x, __nv_bfloat16* h, __nv_bfloat16* l) {
    float xs[4] = {x.x, x.y, x.z, x.w};
#pragma unroll
    for (int j = 0; j < 4; j++) {
        __nv_bfloat16 hv = __float2bfloat16(xs[j]);
        h[j] = hv;
        l[j] = __float2bfloat16(xs[j] - __bfloat162float(hv));
    }
}
__global__ __launch_bounds__(256) void cvt_x_kernel(const float* __restrict__ src) {
    size_t i = ((size_t)blockIdx.x * 256 + threadIdx.x) * 4;
    __nv_bfloat16 h[4], l[4];
    split4(*(const float4*)(src + i), h, l);
    *(uint2*)&g_Xh[i] = *(uint2*)h;
    *(uint2*)&g_Xl[i] = *(uint2*)l;
}
__global__ __launch_bounds__(256) void cvt_w_kernel(const float* __restrict__ src, int w) {
    size_t i = ((size_t)blockIdx.x * 256 + threadIdx.x) * 4;
    __nv_bfloat16 h[4], l[4];
    split4(*(const float4*)(src + i), h, l);
    *(uint2*)&g_Wh[w][i] = *(uint2*)h;
    *(uint2*)&g_Wl[w][i] = *(uint2*)l;
}

// ===========================================================================
// Split-bf16 GEMM on mma.sync: C[m,n] = sum_k A[m,k] * W[n,k]
// CTA 128x128, K-chunk 32, 8 warps (warp tile 32x64), cp.async double buffer,
// ONE __syncthreads per k-chunk, MMAs ordered for accumulator reuse dist 4.
// ===========================================================================
#define KC 32
#define ROWB 80                // padded row stride (bytes): conflict-free ldmatrix
#define MATB (128*ROWB)        // 10240 B per matrix
#define STGB (4*MATB)          // 40960 B per stage
#define NKC (HH/KC)            // 64 k-iterations

__global__ __launch_bounds__(256, 2) void gemm_mma(
    const __nv_bfloat16* __restrict__ xh, const __nv_bfloat16* __restrict__ xl,
    int wbase,
    float* __restrict__ C0, float* __restrict__ C1, float* __restrict__ C2)
{
    extern __shared__ __align__(16) char smem[];
    const uint32_t sb = smem_u32(smem);
    const int tid = threadIdx.x, lane = tid & 31, wid = tid >> 5;
    const int wm = wid >> 1, wn = wid & 1;           // 4x2 warp grid
    const int bm = blockIdx.y * 128, bn = blockIdx.x * 128;
    const int w = wbase + blockIdx.z;
    const __nv_bfloat16* wh = g_Wh[w];
    const __nv_bfloat16* wl = g_Wl[w];
    float* C = (blockIdx.z == 0) ? C0 : (blockIdx.z == 1) ? C1 : C2;

    float acc[2][8][4] = {};

    // cp.async stage loader: 2048 16B vectors, 8 per thread
    auto load_stage = [&](int buf, int k0) {
        const uint32_t sbase = sb + buf * STGB;
#pragma unroll
        for (int i = 0; i < 8; i++) {
            int idx = i * 256 + tid;
            int mat = idx >> 9;          // 0:Ah 1:Al 2:Bh 3:Bl
            int rem = idx & 511;
            int r = rem >> 2, vv = rem & 3;
            const __nv_bfloat16* base = (mat == 0) ? xh : (mat == 1) ? xl
                                      : (mat == 2) ? wh : wl;
            int row0 = (mat < 2) ? bm : bn;
            cp16(sbase + mat * MATB + r * ROWB + vv * 16,
                 base + (size_t)(row0 + r) * HH + k0 + vv * 8);
        }
    };

    const uint32_t aRowOff = (uint32_t)((wm * 32 + (lane & 15)) * ROWB + (lane >> 4) * 16);
    const uint32_t bRowOff = (uint32_t)((wn * 64 + ((lane >> 4) << 3) + (lane & 7)) * ROWB
                                        + ((lane >> 3) & 1) * 16);

    load_stage(0, 0);
    CP_COMMIT();
    CP_WAIT0();
    __syncthreads();

    for (int c = 0; c < NKC; c++) {
        const int buf = c & 1;
        if (c + 1 < NKC) {              // kick next stage before computing
            load_stage(buf ^ 1, (c + 1) * KC);
            CP_COMMIT();
        }
        const uint32_t s0 = sb + buf * STGB;
#pragma unroll
        for (int kg = 0; kg < 2; kg++) {
            const uint32_t kOff = kg * 32;     // 16 bf16 = 32B
            uint32_t ah[2][4], al[2][4];
#pragma unroll
            for (int mt = 0; mt < 2; mt++) {
                ldm_x4(s0 + 0    + mt * 16 * ROWB + kOff + aRowOff, ah[mt]);
                ldm_x4(s0 + MATB + mt * 16 * ROWB + kOff + aRowOff, al[mt]);
            }
#pragma unroll
            for (int p = 0; p < 4; p++) {      // n-tile pairs
                uint32_t bh4[4], bl4[4];
                ldm_x4(s0 + 2*MATB + p * 16 * ROWB + kOff + bRowOff, bh4);
                ldm_x4(s0 + 3*MATB + p * 16 * ROWB + kOff + bRowOff, bl4);
                // product hh — 4 distinct accumulators
                mma16816(acc[0][2*p],   ah[0], &bh4[0]);
                mma16816(acc[1][2*p],   ah[1], &bh4[0]);
                mma16816(acc[0][2*p+1], ah[0], &bh4[2]);
                mma16816(acc[1][2*p+1], ah[1], &bh4[2]);
                // product hl
                mma16816(acc[0][2*p],   ah[0], &bl4[0]);
                mma16816(acc[1][2*p],   ah[1], &bl4[0]);
                mma16816(acc[0][2*p+1], ah[0], &bl4[2]);
                mma16816(acc[1][2*p+1], ah[1], &bl4[2]);
                // product lh
                mma16816(acc[0][2*p],   al[0], &bh4[0]);
                mma16816(acc[1][2*p],   al[1], &bh4[0]);
                mma16816(acc[0][2*p+1], al[0], &bh4[2]);
                mma16816(acc[1][2*p+1], al[1], &bh4[2]);
            }
        }
        if (c + 1 < NKC) {
            CP_WAIT0();
            __syncthreads();            // next buf ready AND this buf free
        }
    }

    // Epilogue
#pragma unroll
    for (int mt = 0; mt < 2; mt++) {
        const int r0 = bm + wm * 32 + mt * 16 + (lane >> 2);
#pragma unroll
        for (int nt = 0; nt < 8; nt++) {
            const int col = bn + wn * 64 + nt * 8 + (lane & 3) * 2;
            *(float2*)&C[(size_t)r0 * HH + col]       = make_float2(acc[mt][nt][0], acc[mt][nt][1]);
            *(float2*)&C[(size_t)(r0 + 8) * HH + col] = make_float2(acc[mt][nt][2], acc[mt][nt][3]);
        }
    }
}

// ---------------------------------------------------------------------------
// Scan pass 1 + fused gating: reads raw i (g_gate) and f (g_v), computes
// gate=sigmoid(f), v=silu(i)*(1-gate), writes them back, accumulates A,B.
// ---------------------------------------------------------------------------
__global__ void scan_part1()
{
    const int d = blockIdx.x * blockDim.x + threadIdx.x;
    const int c = blockIdx.y, b = blockIdx.z;
    size_t base = ((size_t)(b*TT + c*CHUNK))*HH + d;
    float A = 1.0f, Bv = 0.0f;
#pragma unroll 8
    for (int t = 0; t < CHUNK; t++) {
        const size_t o = base + (size_t)t*HH;
        float iv = g_gate[o];
        float fv = g_v[o];
        float gate = sigf(fv);
        float vv = iv * sigf(iv) * (1.0f - gate);
        g_gate[o] = gate;
        g_v[o] = vv;
        Bv = fmaf(gate, Bv, vv);
        A *= gate;
    }
    const size_t co = ((size_t)(b*NCHUNK + c))*HH + d;
    g_Ac[co] = A; g_Bc[co] = Bv;
}
__global__ void scan_part2()
{
    const int idx = blockIdx.x * blockDim.x + threadIdx.x;
    const int b = idx / HH, d = idx % HH;
    float h = 0.0f;
    for (int c = 0; c < NCHUNK; c++) {
        const size_t co = ((size_t)(b*NCHUNK + c))*HH + d;
        g_cr[co] = h;
        h = fmaf(g_Ac[co], h, g_Bc[co]);
    }
}
__global__ void scan_part3()
{
    const int d = blockIdx.x * blockDim.x + threadIdx.x;
    const int c = blockIdx.y, b = blockIdx.z;
    size_t base = ((size_t)(b*TT + c*CHUNK))*HH + d;
    float h = g_cr[((size_t)(b*NCHUNK + c))*HH + d];
#pragma unroll 8
    for (int t = 0; t < CHUNK; t++) {
        const size_t o = base + (size_t)t*HH;
        h = fmaf(g_gate[o], h, g_v[o]);
        g_o[o] = h;
    }
}

// ---------------------------------------------------------------------------
// Gated RMSNorm, vectorized; writes bf16 hi/lo split directly (g_Xh/g_Xl).
// ---------------------------------------------------------------------------
__global__ __launch_bounds__(256) void norm_kernel(const float* __restrict__ w)
{
    const int m = blockIdx.x;
    const size_t row = (size_t)m * HH;
    float s = 0.0f;
#pragma unroll
    for (int it = 0; it < 2; it++) {
        int d4 = (it * 256 + threadIdx.x) * 4;
        float4 x = *(const float4*)&g_o[row + d4];
        s = fmaf(x.x, x.x, fmaf(x.y, x.y, fmaf(x.z, x.z, fmaf(x.w, x.w, s))));
    }
    __shared__ float red[8];
#pragma unroll
    for (int o = 16; o; o >>= 1) s += __shfl_xor_sync(0xffffffffu, s, o);
    if ((threadIdx.x & 31) == 0) red[threadIdx.x >> 5] = s;
    __syncthreads();
    if (threadIdx.x < 8) {
        float t = red[threadIdx.x];
#pragma unroll
        for (int o = 4; o; o >>= 1) t += __shfl_xor_sync(0xffu, t, o);
        if (threadIdx.x == 0) red[0] = t;
    }
    __syncthreads();
    const float rms = rsqrtf(red[0] / (float)HH + 1e-5f);
#pragma unroll
    for (int it = 0; it < 2; it++) {
        int d4 = (it * 256 + threadIdx.x) * 4;
        float4 x  = *(const float4*)&g_o[row + d4];
        float4 gp = *(const float4*)&g_gp[row + d4];
        float4 wv = *(const float4*)&w[d4];
        float y[4] = {
            x.x * rms * wv.x * gp.x * sigf(gp.x),
            x.y * rms * wv.y * gp.y * sigf(gp.y),
            x.z * rms * wv.z * gp.z * sigf(gp.z),
            x.w * rms * wv.w * gp.w * sigf(gp.w)
        };
        __nv_bfloat16 h[4], l[4];
        split4(make_float4(y[0], y[1], y[2], y[3]), h, l);
        *(uint2*)&g_Xh[row + d4] = *(uint2*)h;
        *(uint2*)&g_Xl[row + d4] = *(uint2*)l;
    }
}

// ---------------------------------------------------------------------------
// Launch
// ---------------------------------------------------------------------------
extern "C" void kernel_launch(void* const* d_in, const int* in_sizes, int n_in,
                              void* d_out, int out_size)
{
    const float* X  = (const float*)d_in[0];
    const float* Wi = (const float*)d_in[1];
    const float* Wf = (const float*)d_in[2];
    const float* Wg = (const float*)d_in[3];
    const float* Wo = (const float*)d_in[4];
    const float* gw = (const float*)d_in[5];
    float* out = (float*)d_out;

    cudaFuncSetAttribute(gemm_mma, cudaFuncAttributeMaxDynamicSharedMemorySize, 2 * STGB);

    // bf16 hi/lo splits
    cvt_x_kernel<<<(size_t)MM*HH/1024, 256>>>(X);
    cvt_w_kernel<<<(size_t)HH*HH/1024, 256>>>(Wi, 0);
    cvt_w_kernel<<<(size_t)HH*HH/1024, 256>>>(Wf, 1);
    cvt_w_kernel<<<(size_t)HH*HH/1024, 256>>>(Wg, 2);
    cvt_w_kernel<<<(size_t)HH*HH/1024, 256>>>(Wo, 3);

    float *pi, *pf, *pg2;
    cudaGetSymbolAddress((void**)&pi,  g_gate);
    cudaGetSymbolAddress((void**)&pf,  g_v);
    cudaGetSymbolAddress((void**)&pg2, g_gp);
    const __nv_bfloat16 *xh, *xl;
    cudaGetSymbolAddress((void**)&xh, g_Xh);
    cudaGetSymbolAddress((void**)&xl, g_Xl);

    // i/f/g projections (raw) via tensor cores
    gemm_mma<<<dim3(HH/128, MM/128, 3), 256, 2*STGB>>>(xh, xl, 0, pi, pf, pg2);

    // gating (fused in part1) + linear recurrence
    dim3 scan_grid(HH/256, NCHUNK, BB);
    scan_part1<<<scan_grid, 256>>>();
    scan_part2<<<(BB*HH)/256, 256>>>();
    scan_part3<<<scan_grid, 256>>>();

    // gated RMSNorm -> bf16 split directly
    norm_kernel<<<MM, 256>>>(gw);

    // output projection -> d_out
    gemm_mma<<<dim3(HH/128, MM/128, 1), 256, 2*STGB>>>(xh, xl, 3, out, out, out);
}

// round 6
// speedup vs baseline: 4.4209x; 1.5313x over previous
#include <cuda_runtime.h>
#include <cuda_bf16.h>
#include <cstdint>
#include <math.h>

// Problem constants (fixed: B=4, T=2048, H=2048)
#define BB 4
#define TT 2048
#define HH 2048
#define MM (BB*TT)              // 8192 rows
#define CHUNK 128
#define NCHUNK (TT/CHUNK)       // 16 chunks

// ---------------------------------------------------------------------------
// Scratch (device globals — no runtime allocation allowed)
// ---------------------------------------------------------------------------
__device__ float g_gate[(size_t)MM*HH];   // raw i -> sigmoid(f) after part1
__device__ float g_v[(size_t)MM*HH];      // raw f -> swiglu value after part1
__device__ float g_gp[(size_t)MM*HH];     // raw g projection
__device__ float g_o[(size_t)MM*HH];      // scan output
__device__ float g_Ac[BB*NCHUNK*HH];
__device__ float g_Bc[BB*NCHUNK*HH];
__device__ float g_cr[BB*NCHUNK*HH];
// int8 2-limb quantized operands
__device__ int8_t g_X0[(size_t)MM*HH];    // X limb0 (reused for normed o)
__device__ int8_t g_X1[(size_t)MM*HH];    // X limb1
__device__ int8_t g_W0[4][(size_t)HH*HH];
__device__ int8_t g_W1[4][(size_t)HH*HH];
__device__ float  g_sx[MM];               // per-row scale of X / normed o
__device__ float  g_sw[4][HH];            // per-row scale of each W

__device__ __forceinline__ float sigf(float x) { return 1.0f/(1.0f+__expf(-x)); }

// ---------------------------------------------------------------------------
// PTX helpers (sm_80-era -> valid on compute_100)
// ---------------------------------------------------------------------------
__device__ __forceinline__ uint32_t smem_u32(const void* p) {
    uint32_t a; asm("{ .reg .u64 t; cvta.to.shared.u64 t, %1; cvt.u32.u64 %0, t; }" : "=r"(a) : "l"(p));
    return a;
}
__device__ __forceinline__ void cp16(uint32_t saddr, const void* g) {
    asm volatile("cp.async.cg.shared.global [%0], [%1], 16;" :: "r"(saddr), "l"(g));
}
#define CP_COMMIT() asm volatile("cp.async.commit_group;" ::: "memory")
#define CP_WAIT1()  asm volatile("cp.async.wait_group 1;" ::: "memory")

__device__ __forceinline__ void ldm_x4(uint32_t a, uint32_t* r) {
    asm volatile("ldmatrix.sync.aligned.m8n8.x4.shared.b16 {%0,%1,%2,%3}, [%4];"
        : "=r"(r[0]), "=r"(r[1]), "=r"(r[2]), "=r"(r[3]) : "r"(a));
}
// s8 MMA: m16n8k32, s32 accumulate
__device__ __forceinline__ void mma_s8(int* c, const uint32_t* a, const uint32_t* b) {
    asm volatile("mma.sync.aligned.m16n8k32.row.col.s32.s8.s8.s32 "
        "{%0,%1,%2,%3}, {%4,%5,%6,%7}, {%8,%9}, {%0,%1,%2,%3};"
        : "+r"(c[0]), "+r"(c[1]), "+r"(c[2]), "+r"(c[3])
        : "r"(a[0]), "r"(a[1]), "r"(a[2]), "r"(a[3]), "r"(b[0]), "r"(b[1]));
}

__device__ __forceinline__ uint32_t pack4(int b0, int b1, int b2, int b3) {
    return (uint32_t)(b0 & 255) | ((uint32_t)(b1 & 255) << 8)
         | ((uint32_t)(b2 & 255) << 16) | ((uint32_t)(b3 & 255) << 24);
}

// ---------------------------------------------------------------------------
// Row quantizer: x ~= s*(a0 + a1/128), a0,a1 int8, s = rowmax/127.
// One block per row, 256 threads x 8 elems.
// ---------------------------------------------------------------------------
__global__ __launch_bounds__(256) void quant_rows(
    const float* __restrict__ src, int8_t* __restrict__ d0,
    int8_t* __restrict__ d1, float* __restrict__ sarr)
{
    const int row = blockIdx.x;
    const float* x = src + (size_t)row * HH;
    const int t = threadIdx.x;
    float4 v0 = ((const float4*)x)[t*2];
    float4 v1 = ((const float4*)x)[t*2 + 1];
    float xs[8] = {v0.x, v0.y, v0.z, v0.w, v1.x, v1.y, v1.z, v1.w};
    float m = 0.f;
#pragma unroll
    for (int j = 0; j < 8; j++) m = fmaxf(m, fabsf(xs[j]));
    __shared__ float red[8];
#pragma unroll
    for (int o = 16; o; o >>= 1) m = fmaxf(m, __shfl_xor_sync(0xffffffffu, m, o));
    if ((t & 31) == 0) red[t >> 5] = m;
    __syncthreads();
    if (t < 8) {
        float mm = red[t];
#pragma unroll
        for (int o = 4; o; o >>= 1) mm = fmaxf(mm, __shfl_xor_sync(0xffu, mm, o));
        if (t == 0) red[0] = mm;
    }
    __syncthreads();
    m = red[0];
    const float s = (m > 0.f) ? m / 127.f : 1.f;
    const float inv = 127.f / fmaxf(m, 1e-30f);
    int a0[8], a1[8];
#pragma unroll
    for (int j = 0; j < 8; j++) {
        float q = xs[j] * inv;
        float r0 = rintf(q);
        a0[j] = (int)r0;
        a1[j] = (int)rintf((q - r0) * 128.f);
    }
    ((uint2*)(d0 + (size_t)row * HH))[t] = make_uint2(pack4(a0[0],a0[1],a0[2],a0[3]), pack4(a0[4],a0[5],a0[6],a0[7]));
    ((uint2*)(d1 + (size_t)row * HH))[t] = make_uint2(pack4(a1[0],a1[1],a1[2],a1[3]), pack4(a1[4],a1[5],a1[6],a1[7]));
    if (t == 0) sarr[row] = s;
}

// ===========================================================================
// 2-limb int8 GEMM on mma.sync m16n8k32: C[m,n] = sum_k A[m,k]*W[n,k]
// CTA 128x128, K-chunk 64 (2 k32 steps), 8 warps (32x64), 3-stage cp.async.
// Smem per stage: A0 | A1 | B0 | B1, each 128 rows x 64B padded to 80B.
// C = sA[m]*sB[n]*(P + Q/128), P = a0w0, Q = a0w1 + a1w0 (a1w1 dropped).
// ===========================================================================
#define KC 64
#define ROWB 80                // conflict-free ldmatrix padding (proven R4/R5)
#define MATB (128*ROWB)        // 10240 B per matrix
#define STGB (4*MATB)          // 40960 B per stage
#define NKC (HH/KC)            // 32 k-iterations
#define NSTG 3

__global__ __launch_bounds__(256, 1) void gemm_mma(
    const int8_t* __restrict__ x0, const int8_t* __restrict__ x1,
    const float* __restrict__ sA, int wbase,
    float* __restrict__ C0, float* __restrict__ C1, float* __restrict__ C2)
{
    extern __shared__ __align__(16) char smem[];
    const uint32_t sb = smem_u32(smem);
    const int tid = threadIdx.x, lane = tid & 31, wid = tid >> 5;
    const int wm = wid >> 1, wn = wid & 1;           // 4x2 warp grid
    const int bm = blockIdx.y * 128, bn = blockIdx.x * 128;
    const int w = wbase + blockIdx.z;
    const int8_t* w0 = g_W0[w];
    const int8_t* w1 = g_W1[w];
    const float* sB = g_sw[w];
    float* C = (blockIdx.z == 0) ? C0 : (blockIdx.z == 1) ? C1 : C2;

    int P[2][8][4] = {}, Q[2][8][4] = {};

    // stage loader: 4 mats x 128 rows x 4 16B-vectors = 2048 vecs, 8/thread
    auto load_stage = [&](int buf, int k0) {
        const uint32_t sbase = sb + buf * STGB;
#pragma unroll
        for (int i = 0; i < 8; i++) {
            int idx = i * 256 + tid;
            int mat = idx >> 9;          // 0:A0 1:A1 2:B0 3:B1
            int rem = idx & 511;
            int r = rem >> 2, vv = rem & 3;
            const int8_t* base = (mat == 0) ? x0 : (mat == 1) ? x1
                               : (mat == 2) ? w0 : w1;
            int row0 = (mat < 2) ? bm : bn;
            cp16(sbase + mat * MATB + r * ROWB + vv * 16,
                 base + (size_t)(row0 + r) * HH + k0 + vv * 16);
        }
    };

    const uint32_t aRowOff = (uint32_t)((wm * 32 + (lane & 15)) * ROWB + (lane >> 4) * 16);
    const uint32_t bRowOff = (uint32_t)((wn * 64 + ((lane >> 4) << 3) + (lane & 7)) * ROWB
                                        + ((lane >> 3) & 1) * 16);

    load_stage(0, 0);      CP_COMMIT();
    load_stage(1, KC);     CP_COMMIT();

    for (int c = 0; c < NKC; c++) {
        CP_WAIT1();                         // stage c landed (c+1 may be in flight)
        __syncthreads();                    // also: all warps done with stage c-1's buffer
        if (c + 2 < NKC) { load_stage((c + 2) % NSTG, (c + 2) * KC); CP_COMMIT(); }
        else CP_COMMIT();                   // keep group accounting uniform

        const uint32_t s0 = sb + (c % NSTG) * STGB;
#pragma unroll
        for (int ks = 0; ks < 2; ks++) {
            const uint32_t kOff = ks * 32;          // 32 int8 = 32B per k32 step
            uint32_t a0f[2][4], a1f[2][4];
#pragma unroll
            for (int mt = 0; mt < 2; mt++) {
                ldm_x4(s0 + 0    + mt * 16 * ROWB + kOff + aRowOff, a0f[mt]);
                ldm_x4(s0 + MATB + mt * 16 * ROWB + kOff + aRowOff, a1f[mt]);
            }
#pragma unroll
            for (int p = 0; p < 4; p++) {
                uint32_t b0f[4], b1f[4];
                ldm_x4(s0 + 2*MATB + p * 16 * ROWB + kOff + bRowOff, b0f);
                ldm_x4(s0 + 3*MATB + p * 16 * ROWB + kOff + bRowOff, b1f);
                // P: a0*b0
                mma_s8(P[0][2*p],   a0f[0], &b0f[0]);
                mma_s8(P[1][2*p],   a0f[1], &b0f[0]);
                mma_s8(P[0][2*p+1], a0f[0], &b0f[2]);
                mma_s8(P[1][2*p+1], a0f[1], &b0f[2]);
                // Q: a0*b1
                mma_s8(Q[0][2*p],   a0f[0], &b1f[0]);
                mma_s8(Q[1][2*p],   a0f[1], &b1f[0]);
                mma_s8(Q[0][2*p+1], a0f[0], &b1f[2]);
                mma_s8(Q[1][2*p+1], a0f[1], &b1f[2]);
                // Q: a1*b0
                mma_s8(Q[0][2*p],   a1f[0], &b0f[0]);
                mma_s8(Q[1][2*p],   a1f[1], &b0f[0]);
                mma_s8(Q[0][2*p+1], a1f[0], &b0f[2]);
                mma_s8(Q[1][2*p+1], a1f[1], &b0f[2]);
            }
        }
    }

    // Epilogue: C = sA[r]*sB[n]*(P + Q/128)
#pragma unroll
    for (int mt = 0; mt < 2; mt++) {
        const int r0 = bm + wm * 32 + mt * 16 + (lane >> 2);
        const float sa0 = sA[r0], sa1 = sA[r0 + 8];
#pragma unroll
        for (int nt = 0; nt < 8; nt++) {
            const int col = bn + wn * 64 + nt * 8 + (lane & 3) * 2;
            const float sb0 = sB[col], sb1 = sB[col + 1];
            const int* Pp = P[mt][nt];
            const int* Qp = Q[mt][nt];
            float c0 = sa0 * sb0 * ((float)Pp[0] + (float)Qp[0] * (1.f/128.f));
            float c1 = sa0 * sb1 * ((float)Pp[1] + (float)Qp[1] * (1.f/128.f));
            float c2 = sa1 * sb0 * ((float)Pp[2] + (float)Qp[2] * (1.f/128.f));
            float c3 = sa1 * sb1 * ((float)Pp[3] + (float)Qp[3] * (1.f/128.f));
            *(float2*)&C[(size_t)r0 * HH + col]       = make_float2(c0, c1);
            *(float2*)&C[(size_t)(r0 + 8) * HH + col] = make_float2(c2, c3);
        }
    }
}

// ---------------------------------------------------------------------------
// Scan pass 1 + fused gating
// ---------------------------------------------------------------------------
__global__ void scan_part1()
{
    const int d = blockIdx.x * blockDim.x + threadIdx.x;
    const int c = blockIdx.y, b = blockIdx.z;
    size_t base = ((size_t)(b*TT + c*CHUNK))*HH + d;
    float A = 1.0f, Bv = 0.0f;
#pragma unroll 8
    for (int t = 0; t < CHUNK; t++) {
        const size_t o = base + (size_t)t*HH;
        float iv = g_gate[o];
        float fv = g_v[o];
        float gate = sigf(fv);
        float vv = iv * sigf(iv) * (1.0f - gate);
        g_gate[o] = gate;
        g_v[o] = vv;
        Bv = fmaf(gate, Bv, vv);
        A *= gate;
    }
    const size_t co = ((size_t)(b*NCHUNK + c))*HH + d;
    g_Ac[co] = A; g_Bc[co] = Bv;
}
__global__ void scan_part2()
{
    const int idx = blockIdx.x * blockDim.x + threadIdx.x;
    const int b = idx / HH, d = idx % HH;
    float h = 0.0f;
    for (int c = 0; c < NCHUNK; c++) {
        const size_t co = ((size_t)(b*NCHUNK + c))*HH + d;
        g_cr[co] = h;
        h = fmaf(g_Ac[co], h, g_Bc[co]);
    }
}
__global__ void scan_part3()
{
    const int d = blockIdx.x * blockDim.x + threadIdx.x;
    const int c = blockIdx.y, b = blockIdx.z;
    size_t base = ((size_t)(b*TT + c*CHUNK))*HH + d;
    float h = g_cr[((size_t)(b*NCHUNK + c))*HH + d];
#pragma unroll 8
    for (int t = 0; t < CHUNK; t++) {
        const size_t o = base + (size_t)t*HH;
        h = fmaf(g_gate[o], h, g_v[o]);
        g_o[o] = h;
    }
}

// ---------------------------------------------------------------------------
// Gated RMSNorm; quantizes its output row directly into g_X0/g_X1/g_sx.
// ---------------------------------------------------------------------------
__global__ __launch_bounds__(256) void norm_kernel(const float* __restrict__ w)
{
    const int m = blockIdx.x;
    const size_t row = (size_t)m * HH;
    const int t = threadIdx.x;
    float s = 0.0f;
#pragma unroll
    for (int it = 0; it < 2; it++) {
        int d4 = (it * 256 + t) * 4;
        float4 x = *(const float4*)&g_o[row + d4];
        s = fmaf(x.x, x.x, fmaf(x.y, x.y, fmaf(x.z, x.z, fmaf(x.w, x.w, s))));
    }
    __shared__ float red[8];
#pragma unroll
    for (int o = 16; o; o >>= 1) s += __shfl_xor_sync(0xffffffffu, s, o);
    if ((t & 31) == 0) red[t >> 5] = s;
    __syncthreads();
    if (t < 8) {
        float tt = red[t];
#pragma unroll
        for (int o = 4; o; o >>= 1) tt += __shfl_xor_sync(0xffu, tt, o);
        if (t == 0) red[0] = tt;
    }
    __syncthreads();
    const float rms = rsqrtf(red[0] / (float)HH + 1e-5f);

    // compute y, track row max
    float y[8];
    float mx = 0.f;
#pragma unroll
    for (int it = 0; it < 2; it++) {
        int d4 = (it * 256 + t) * 4;
        float4 x  = *(const float4*)&g_o[row + d4];
        float4 gp = *(const float4*)&g_gp[row + d4];
        float4 wv = *(const float4*)&w[d4];
        y[it*4+0] = x.x * rms * wv.x * gp.x * sigf(gp.x);
        y[it*4+1] = x.y * rms * wv.y * gp.y * sigf(gp.y);
        y[it*4+2] = x.z * rms * wv.z * gp.z * sigf(gp.z);
        y[it*4+3] = x.w * rms * wv.w * gp.w * sigf(gp.w);
#pragma unroll
        for (int j = 0; j < 4; j++) mx = fmaxf(mx, fabsf(y[it*4+j]));
    }
    __syncthreads();
#pragma unroll
    for (int o = 16; o; o >>= 1) mx = fmaxf(mx, __shfl_xor_sync(0xffffffffu, mx, o));
    if ((t & 31) == 0) red[t >> 5] = mx;
    __syncthreads();
    if (t < 8) {
        float mm = red[t];
#pragma unroll
        for (int o = 4; o; o >>= 1) mm = fmaxf(mm, __shfl_xor_sync(0xffu, mm, o));
        if (t == 0) red[0] = mm;
    }
    __syncthreads();
    mx = red[0];
    const float sc = (mx > 0.f) ? mx / 127.f : 1.f;
    const float inv = 127.f / fmaxf(mx, 1e-30f);
#pragma unroll
    for (int it = 0; it < 2; it++) {
        int d4 = (it * 256 + t) * 4;
        int a0[4], a1[4];
#pragma unroll
        for (int j = 0; j < 4; j++) {
            float q = y[it*4+j] * inv;
            float r0 = rintf(q);
            a0[j] = (int)r0;
            a1[j] = (int)rintf((q - r0) * 128.f);
        }
        *(uint32_t*)&g_X0[row + d4] = pack4(a0[0],a0[1],a0[2],a0[3]);
        *(uint32_t*)&g_X1[row + d4] = pack4(a1[0],a1[1],a1[2],a1[3]);
    }
    if (t == 0) g_sx[m] = sc;
}

// ---------------------------------------------------------------------------
// Launch
// ---------------------------------------------------------------------------
extern "C" void kernel_launch(void* const* d_in, const int* in_sizes, int n_in,
                              void* d_out, int out_size)
{
    const float* X  = (const float*)d_in[0];
    const float* Wi = (const float*)d_in[1];
    const float* Wf = (const float*)d_in[2];
    const float* Wg = (const float*)d_in[3];
    const float* Wo = (const float*)d_in[4];
    const float* gw = (const float*)d_in[5];
    float* out = (float*)d_out;

    cudaFuncSetAttribute(gemm_mma, cudaFuncAttributeMaxDynamicSharedMemorySize, NSTG * STGB);

    int8_t *x0, *x1, *w0b, *w1b;
    float *sx, *swb;
    cudaGetSymbolAddress((void**)&x0,  g_X0);
    cudaGetSymbolAddress((void**)&x1,  g_X1);
    cudaGetSymbolAddress((void**)&w0b, g_W0);
    cudaGetSymbolAddress((void**)&w1b, g_W1);
    cudaGetSymbolAddress((void**)&sx,  g_sx);
    cudaGetSymbolAddress((void**)&swb, g_sw);
    float *pi, *pf, *pg2;
    cudaGetSymbolAddress((void**)&pi,  g_gate);
    cudaGetSymbolAddress((void**)&pf,  g_v);
    cudaGetSymbolAddress((void**)&pg2, g_gp);

    // quantize X and the 4 weights (2-limb int8, per-row scales)
    quant_rows<<<MM, 256>>>(X, x0, x1, sx);
    quant_rows<<<HH, 256>>>(Wi, w0b + 0*(size_t)HH*HH, w1b + 0*(size_t)HH*HH, swb + 0*HH);
    quant_rows<<<HH, 256>>>(Wf, w0b + 1*(size_t)HH*HH, w1b + 1*(size_t)HH*HH, swb + 1*HH);
    quant_rows<<<HH, 256>>>(Wg, w0b + 2*(size_t)HH*HH, w1b + 2*(size_t)HH*HH, swb + 2*HH);
    quant_rows<<<HH, 256>>>(Wo, w0b + 3*(size_t)HH*HH, w1b + 3*(size_t)HH*HH, swb + 3*HH);

    // i/f/g projections (raw) via int8 tensor cores
    gemm_mma<<<dim3(HH/128, MM/128, 3), 256, NSTG*STGB>>>(x0, x1, sx, 0, pi, pf, pg2);

    // gating (fused) + linear recurrence
    dim3 scan_grid(HH/256, NCHUNK, BB);
    scan_part1<<<scan_grid, 256>>>();
    scan_part2<<<(BB*HH)/256, 256>>>();
    scan_part3<<<scan_grid, 256>>>();

    // gated RMSNorm -> quantized o (reuses g_X0/g_X1/g_sx)
    norm_kernel<<<MM, 256>>>(gw);

    // output projection -> d_out
    gemm_mma<<<dim3(HH/128, MM/128, 1), 256, NSTG*STGB>>>(x0, x1, sx, 3, out, out, out);
}